// round 14
// baseline (speedup 1.0000x reference)
#include <cuda_runtime.h>
#include <cuda_fp16.h>
#include <cstdint>

#define TSTEPS 60
#define HDIM   50
#define BLOCK  256
#define ELPB   64
#define GRID   256
#define NTT    26                 // n-tiles (13 pairs x 16 gate cols)

// ---- smem byte layout (per CTA, ~72 KB -> 2 CTAs/SM) ----
#define ABASE  0
#define ABUF   8192                // per buffer: 4 mt x 4 kt x 512B (fp16)
#define BBASE  (2 * ABUF)          // 16384
#define XBASE  (BBASE + NTT * 1024)          // 43008
#define WLBASE (XBASE + ELPB * 61 * 4)       // 58624
#define OPBASE (WLBASE + TSTEPS * HDIM * 4)  // 70624
#define SMTOT  (OPBASE + 4 * ELPB * 4)       // 71648

__device__ __forceinline__ float tanha(float x) {
    float r; asm("tanh.approx.f32 %0, %1;" : "=f"(r) : "f"(x)); return r;
}
__device__ __forceinline__ float sigt(float x) {
    return fmaf(0.5f, tanha(0.5f * x), 0.5f);
}
__device__ __forceinline__ uint32_t pk2(float lo, float hi) {
    uint32_t r; asm("cvt.rn.f16x2.f32 %0, %1, %2;" : "=r"(r) : "f"(hi), "f"(lo));
    return r;
}
__device__ __forceinline__ void mma16816h(float* d, const uint32_t* a, const uint32_t* b) {
    asm volatile(
        "mma.sync.aligned.m16n8k16.row.col.f32.f16.f16.f32 "
        "{%0,%1,%2,%3}, {%4,%5,%6,%7}, {%8,%9}, {%0,%1,%2,%3};"
        : "+f"(d[0]), "+f"(d[1]), "+f"(d[2]), "+f"(d[3])
        : "r"(a[0]), "r"(a[1]), "r"(a[2]), "r"(a[3]), "r"(b[0]), "r"(b[1]));
}
__device__ __forceinline__ void bargrp(int id) {
    asm volatile("bar.sync %0, 128;" :: "r"(id) : "memory");
}

// store h2 = (h(row gr), h(row gr+8)) of m-tile mt at A col k
__device__ __forceinline__ void store_h2pair(char* sm, int buf, int mt, int gr,
                                             int k, uint32_t h2) {
    const int kt = k >> 4, kin = k & 15;
    const int tg = (kin >> 1) & 3;
    const int base = buf * ABUF + (mt * 4 + kt) * 512 + (gr * 4 + tg) * 16 +
                     ((kin >= 8) ? 8 : 0) + (k & 1) * 2;
    *(uint16_t*)(sm + ABASE + base)     = (uint16_t)h2;
    *(uint16_t*)(sm + ABASE + base + 4) = (uint16_t)(h2 >> 16);
}
// store f16x2 pair at cols (k, k+1) of element row e, k even
__device__ __forceinline__ void store_hpair(char* sm, int buf, int e, int k,
                                            float v0, float v1) {
    const int mt  = e >> 4, row = e & 15;
    const int kt  = k >> 4, kin = k & 15;
    const int tg  = (kin >> 1) & 3;
    const int ridx = ((row >= 8) ? 1 : 0) + ((kin >= 8) ? 2 : 0);
    const int lt   = (row & 7) * 4 + tg;
    const uint32_t hreg = pk2(v0, v1);
    const int base = buf * ABUF + (mt * 4 + kt) * 512 + lt * 16 + ridx * 4;
    *(uint32_t*)(sm + ABASE + base) = hreg;
}

// the recurrence, specialized on pair count for straight-line code
template<int PCNT>
__device__ __forceinline__ void run_steps(char* sm, const float* xs,
                                          int grp, int lane, int pLo,
                                          int barid, bool doX, float* acc)
{
    const int gr  = lane >> 2;
    const int tig = lane & 3;
    const int mt0 = 2 * grp, mt1 = 2 * grp + 1;

    float cst[PCNT * 4];
#pragma unroll
    for (int i = 0; i < PCNT * 4; i++) cst[i] = 0.0f;

    for (int t = 0; t < TSTEPS; t++) {
        const int cur = t & 1, nxt = cur ^ 1;

        uint32_t aH0[4][4], aH1[4][4];
        const char* ab0 = sm + ABASE + cur * ABUF + (mt0 * 4) * 512 + lane * 16;
        const char* ab1 = ab0 + 4 * 512;
#pragma unroll
        for (int kt = 0; kt < 4; kt++) {
            *(uint4*)aH0[kt] = *(const uint4*)(ab0 + kt * 512);
            *(uint4*)aH1[kt] = *(const uint4*)(ab1 + kt * 512);
        }

        const float* wl = (const float*)(sm + WLBASE) + t * HDIM;

#pragma unroll
        for (int pp = 0; pp < PCNT; pp++) {
            const int p    = pLo + pp;
            const int cell = 4 * p + tig;

            uint32_t bif[8], bgo[8];
            const char* bbE = sm + BBASE + (2 * p) * 1024 + lane * 16;
            *(uint4*)bif       = *(const uint4*)bbE;
            *(uint4*)(bif + 4) = *(const uint4*)(bbE + 512);
            *(uint4*)bgo       = *(const uint4*)(bbE + 1024);
            *(uint4*)(bgo + 4) = *(const uint4*)(bbE + 1536);

            float dif0[4] = {0, 0, 0, 0}, dif1[4] = {0, 0, 0, 0};
            float dgo0[4] = {0, 0, 0, 0}, dgo1[4] = {0, 0, 0, 0};
#pragma unroll
            for (int kt = 0; kt < 4; kt++) {
                mma16816h(dif0, aH0[kt], bif + 2 * kt);
                mma16816h(dif1, aH1[kt], bif + 2 * kt);
                mma16816h(dgo0, aH0[kt], bgo + 2 * kt);
                mma16816h(dgo1, aH1[kt], bgo + 2 * kt);
            }

            const bool realc = (cell < HDIM);
            const float wv = realc ? wl[cell] : 0.0f;
            const int ci = pp * 4;

            // ---- rows (gr, gr+8) of m-tile mt0 : all-fp32 activations ----
            {
                const float i0 = sigt(dif0[0]), f0 = sigt(dif0[1]);
                const float g0 = tanha(dgo0[0]), o0 = sigt(dgo0[1]);
                cst[ci] = fmaf(f0, cst[ci], i0 * g0);
                const float h0 = o0 * tanha(cst[ci]);
                const float i1 = sigt(dif0[2]), f1 = sigt(dif0[3]);
                const float g1 = tanha(dgo0[2]), o1 = sigt(dgo0[3]);
                cst[ci + 1] = fmaf(f1, cst[ci + 1], i1 * g1);
                const float h1 = o1 * tanha(cst[ci + 1]);
                acc[0] = fmaf(h0, wv, acc[0]);
                acc[1] = fmaf(h1, wv, acc[1]);
                if (realc) store_h2pair(sm, nxt, mt0, gr, cell, pk2(h0, h1));
            }
            // ---- rows (gr+16, gr+24) of m-tile mt1 ----
            {
                const float i0 = sigt(dif1[0]), f0 = sigt(dif1[1]);
                const float g0 = tanha(dgo1[0]), o0 = sigt(dgo1[1]);
                cst[ci + 2] = fmaf(f0, cst[ci + 2], i0 * g0);
                const float h0 = o0 * tanha(cst[ci + 2]);
                const float i1 = sigt(dif1[2]), f1 = sigt(dif1[3]);
                const float g1 = tanha(dgo1[2]), o1 = sigt(dgo1[3]);
                cst[ci + 3] = fmaf(f1, cst[ci + 3], i1 * g1);
                const float h1 = o1 * tanha(cst[ci + 3]);
                acc[2] = fmaf(h0, wv, acc[2]);
                acc[3] = fmaf(h1, wv, acc[3]);
                if (realc) store_h2pair(sm, nxt, mt1, gr, cell, pk2(h0, h1));
            }
        }

        if (doX && t + 1 < TSTEPS) {
            const int er = grp * 32 + lane;
            store_hpair(sm, nxt, er, 50, 1.0f, xs[er * 61 + t + 1]);
        }

        bargrp(barid);
    }
}

__global__ void __launch_bounds__(BLOCK, 2)
lstm_occ2_kernel(const float* __restrict__ x_g,
                 const float* __restrict__ wih_g,
                 const float* __restrict__ whh_g,
                 const float* __restrict__ bih_g,
                 const float* __restrict__ bhh_g,
                 const float* __restrict__ wlin_g,
                 const float* __restrict__ blin_g,
                 float* __restrict__ out_g)
{
    extern __shared__ char sm[];
    const int tid  = threadIdx.x;
    const int lane = tid & 31;
    const int wid  = tid >> 5;
    const int grp  = wid >> 2;          // 0..1: 32-element group
    const int q    = wid & 3;           // pair-quarter within group

    // ---- zero both A buffers ----
    for (int i = tid; i < (2 * ABUF) / 16; i += BLOCK)
        ((uint4*)(sm + ABASE))[i] = make_uint4(0, 0, 0, 0);

    // ---- build B fragments (fp16) with gate-pair column order ----
    for (int idx = tid; idx < NTT * 2 * 32; idx += BLOCK) {
        int r         = idx;
        const int nt  = r / 64;  r %= 64;
        const int kt2 = r / 32;
        const int ln  = r % 32;
        const int bgr = ln >> 2, btig = ln & 3;
        const int p    = nt >> 1, oddnt = nt & 1;
        const int u    = bgr >> 1, v = bgr & 1;
        const int cell = 4 * p + u;
        const int gate = oddnt ? (v ? 3 : 2) : (v ? 1 : 0);     // i,f | g,o
        const int grow = (gate == 0 ? 0 : gate == 1 ? 50 : gate == 2 ? 100 : 150);
        const int row  = grow + cell;
        const bool realc = (cell < HDIM);
        uint32_t u4[4];
#pragma unroll
        for (int ktl = 0; ktl < 2; ktl++) {
            const int kt = 2 * kt2 + ktl;
            const int kk[4] = {kt * 16 + 2 * btig,     kt * 16 + 2 * btig + 1,
                               kt * 16 + 2 * btig + 8, kt * 16 + 2 * btig + 9};
            unsigned short vv[4];
#pragma unroll
            for (int j = 0; j < 4; j++) {
                float w = 0.0f;
                const int k = kk[j];
                if (realc) {
                    if (k < HDIM)     w = whh_g[row * HDIM + k];
                    else if (k == 50) w = bih_g[row] + bhh_g[row];
                    else if (k == 51) w = wih_g[row];
                }
                vv[j] = __half_as_ushort(__float2half_rn(w));
            }
            u4[2 * ktl]     = ((uint32_t)vv[1] << 16) | vv[0];
            u4[2 * ktl + 1] = ((uint32_t)vv[3] << 16) | vv[2];
        }
        *(uint4*)(sm + BBASE + nt * 1024 + kt2 * 512 + ln * 16) =
            make_uint4(u4[0], u4[1], u4[2], u4[3]);
    }

    // ---- stage x and wlin ----
    {
        const float* xin = x_g + (size_t)blockIdx.x * ELPB * TSTEPS;
        for (int i = tid; i < ELPB * TSTEPS; i += BLOCK) {
            int el = i / TSTEPS, t = i % TSTEPS;
            ((float*)(sm + XBASE))[el * 61 + t] = xin[i];
        }
    }
    for (int i = tid; i < TSTEPS * HDIM; i += BLOCK)
        ((float*)(sm + WLBASE))[i] = wlin_g[i];
    __syncthreads();

    if (tid < ELPB)
        store_hpair(sm, 0, tid, 50, 1.0f, ((float*)(sm + XBASE))[tid * 61]);
    __syncthreads();

    static const int pLoT[4] = {0, 4, 7, 10};
    const int pLo  = pLoT[q];
    const int barid = 1 + grp;
    const float* xs = (const float*)(sm + XBASE);

    float acc[4] = {0.0f, 0.0f, 0.0f, 0.0f};
    if (q == 0)
        run_steps<4>(sm, xs, grp, lane, pLo, barid, false, acc);
    else
        run_steps<3>(sm, xs, grp, lane, pLo, barid, q == 3, acc);

    // ---- reductions: over tig, then across the 4 warps of the group ----
    const int gr = lane >> 2;
    const int tig = lane & 3;
    const int r0 = grp * 32 + gr;
#pragma unroll
    for (int rr = 0; rr < 4; rr++) {
        acc[rr] += __shfl_xor_sync(0xffffffffu, acc[rr], 1);
        acc[rr] += __shfl_xor_sync(0xffffffffu, acc[rr], 2);
    }
    float* op = (float*)(sm + OPBASE);
    if (tig == 0) {
#pragma unroll
        for (int rr = 0; rr < 4; rr++)
            op[q * ELPB + r0 + rr * 8] = acc[rr];
    }
    __syncthreads();
    if (tid < ELPB) {
        const float s = op[tid] + op[ELPB + tid] + op[2 * ELPB + tid] +
                        op[3 * ELPB + tid];
        out_g[(size_t)blockIdx.x * ELPB + tid] = s + blin_g[0];
    }
}

extern "C" void kernel_launch(void* const* d_in, const int* in_sizes, int n_in,
                              void* d_out, int out_size)
{
    const float* x    = (const float*)d_in[0];
    const float* wih  = (const float*)d_in[1];
    const float* whh  = (const float*)d_in[2];
    const float* bih  = (const float*)d_in[3];
    const float* bhh  = (const float*)d_in[4];
    const float* wlin = (const float*)d_in[5];
    const float* blin = (const float*)d_in[6];
    float* out = (float*)d_out;

    cudaFuncSetAttribute(lstm_occ2_kernel,
                         cudaFuncAttributeMaxDynamicSharedMemorySize, SMTOT);
    lstm_occ2_kernel<<<GRID, BLOCK, SMTOT>>>(x, wih, whh, bih, bhh, wlin, blin, out);
}